// round 1
// baseline (speedup 1.0000x reference)
#include <cuda_runtime.h>
#include <math.h>

// ---------------------------------------------------------------------------
// Problem constants
// ---------------------------------------------------------------------------
#define B_   2
#define P_   4000
#define NP_  4096
#define D_   64
#define M_   512
#define K_   8
#define NX_  432
#define NY_  496
#define HW_  (NX_ * NY_)          // 214272

// Output layout (floats), concatenated in return order:
//   out0 spatial_features        [B,128,HW]  size S0
//   out1 spatial_features_point  [B,128,HW]  size S0
//   out2 spatial_scale_features  [B, 64,HW]  size S2
//   out3 point_positive          [B*P,64]
//   out4 memory_positive         [B*P,64]
#define S0_   ((size_t)B_ * 128 * HW_)              // 54,853,632
#define S2_   ((size_t)B_ * 64 * HW_)               // 27,426,816
#define OFF1_ (S0_)
#define OFF2_ (2 * S0_)
#define OFF3_ (2 * S0_ + S2_)                        // 137,134,080
#define OFF4_ (OFF3_ + (size_t)B_ * P_ * D_)         // 137,646,080

// Attention kernel tiling
#define TILE_P 64
#define TILE_T 128
#define PITCH  68        // 68*4=272 B; 272 mod 128 = 16 -> conflict-free LDS.128
#define NTHR   256

// dynamic shared layout (bytes)
#define SM_PL  0
#define SM_PT  (TILE_P * PITCH * 4)                    // 17408
#define SM_TV  (SM_PT + 2 * TILE_T * PITCH * 4)        // 87040
#define SM_TI  (SM_TV + TILE_P * 32 * 8 * 4)           // 152576
#define SM_W   (SM_TI + TILE_P * 32 * 8 * 2)           // 185344
#define SM_WI  (SM_W + TILE_P * 8 * 4)                 // 187392
#define SMEM_BYTES (SM_WI + TILE_P * 8 * 4)            // 189440

// scratch for duplicate-index resolution (last write wins)
__device__ int g_winner[B_ * HW_];

// ---------------------------------------------------------------------------
// helpers
// ---------------------------------------------------------------------------
__device__ __forceinline__ void cp16(void* dst, const void* src) {
    unsigned a = (unsigned)__cvta_generic_to_shared(dst);
    asm volatile("cp.async.cg.shared.global [%0], [%1], 16;" :: "r"(a), "l"(src));
}
__device__ __forceinline__ void cp_commit() {
    asm volatile("cp.async.commit_group;" ::: "memory");
}
__device__ __forceinline__ void cp_wait_all() {
    asm volatile("cp.async.wait_group 0;" ::: "memory");
}
// packed f32x2 FMA: 2x throughput vs FFMA-3reg on sm_103a
__device__ __forceinline__ void fma2(unsigned long long& acc,
                                     unsigned long long a, unsigned long long b) {
    asm volatile("fma.rn.f32x2 %0, %1, %2, %0;" : "+l"(acc) : "l"(a), "l"(b));
}

// ---------------------------------------------------------------------------
// Fused GEMM + top-8 + softmax + weighted-gather kernel.
//   For each pillar p (per batch b): logits l_n = pillar_p . vec_n over NPTS
//   vectors; take top-8, softmax them, output sum_k w_k * vec_{idx_k}.
// Block: 64 pillars, 256 threads. Thread (tx=t&31, ty=t>>5) owns an 8x4
// micro-tile: pillar rows {ty+8i}, point rows {tx+32j} of a 128-point tile.
// Running per-thread top-8 lives in shared (per (pillar,tx) 8 slots), with the
// current min cached in a register so the hot path is one compare.
// ---------------------------------------------------------------------------
template <int NPTS>
__global__ void __launch_bounds__(NTHR, 1)
attn_kernel(const float* __restrict__ pillars,   // [B,P,64]
            const float* __restrict__ vecs,      // [?,NPTS,64]
            int vstride,                          // batch stride (elements), 0 for shared W
            float* __restrict__ out_pos)          // [B*P,64]
{
    extern __shared__ char smem[];
    float*          s_pl = (float*)(smem + SM_PL);
    float*          s_pt = (float*)(smem + SM_PT);
    float*          s_tv = (float*)(smem + SM_TV);
    unsigned short* s_ti = (unsigned short*)(smem + SM_TI);
    float*          s_w  = (float*)(smem + SM_W);
    int*            s_wi = (int*)(smem + SM_WI);

    const int t  = threadIdx.x;
    const int tx = t & 31;
    const int ty = t >> 5;
    const int b  = blockIdx.y;
    const int p0 = blockIdx.x * TILE_P;
    const int pvalid = min(TILE_P, P_ - p0);
    const float* __restrict__ vb = vecs + (size_t)b * vstride;
    const float* __restrict__ pb = pillars + ((size_t)b * P_ + p0) * D_;

    // init top-k value slots
#pragma unroll
    for (int q = 0; q < (TILE_P * 32 * 8) / NTHR; ++q)
        s_tv[t + q * NTHR] = -INFINITY;

    // load pillar tile (zero-pad tail rows)
#pragma unroll
    for (int q = 0; q < 4; ++q) {
        int lin = t + q * NTHR;
        int r = lin >> 4, c = (lin & 15) << 2;
        float4 v = make_float4(0.f, 0.f, 0.f, 0.f);
        if (r < pvalid) v = *(const float4*)(pb + r * D_ + c);
        *(float4*)(s_pl + r * PITCH + c) = v;
    }

    // prefetch point tile 0
#pragma unroll
    for (int q = 0; q < 8; ++q) {
        int lin = t + q * NTHR;
        int r = lin >> 4, c = (lin & 15) << 2;
        cp16(s_pt + r * PITCH + c, vb + r * D_ + c);
    }
    cp_commit();
    __syncthreads();

    float vmin[8];
#pragma unroll
    for (int i = 0; i < 8; ++i) vmin[i] = -INFINITY;
    const int tk_base = tx * 8;

    constexpr int NT = NPTS / TILE_T;
    for (int tile = 0; tile < NT; ++tile) {
        float* buf = s_pt + (tile & 1) * (TILE_T * PITCH);
        cp_wait_all();
        __syncthreads();   // data ready + all prior reads of the other buffer done
        if (tile + 1 < NT) {
            float* nb = s_pt + ((tile + 1) & 1) * (TILE_T * PITCH);
            const float* src = vb + (size_t)(tile + 1) * TILE_T * D_;
#pragma unroll
            for (int q = 0; q < 8; ++q) {
                int lin = t + q * NTHR;
                int r = lin >> 4, c = (lin & 15) << 2;
                cp16(nb + r * PITCH + c, src + r * D_ + c);
            }
            cp_commit();
        }

        unsigned long long acc[8][4];
#pragma unroll
        for (int i = 0; i < 8; ++i)
#pragma unroll
            for (int j = 0; j < 4; ++j) acc[i][j] = 0ull;

#pragma unroll
        for (int dc = 0; dc < D_; dc += 4) {
            unsigned long long a0[8], a1[8], x0[4], x1[4];
#pragma unroll
            for (int i = 0; i < 8; ++i) {
                ulonglong2 v = *(const ulonglong2*)(s_pl + (ty + 8 * i) * PITCH + dc);
                a0[i] = v.x; a1[i] = v.y;
            }
#pragma unroll
            for (int j = 0; j < 4; ++j) {
                ulonglong2 v = *(const ulonglong2*)(buf + (tx + 32 * j) * PITCH + dc);
                x0[j] = v.x; x1[j] = v.y;
            }
#pragma unroll
            for (int i = 0; i < 8; ++i)
#pragma unroll
                for (int j = 0; j < 4; ++j) {
                    fma2(acc[i][j], a0[i], x0[j]);
                    fma2(acc[i][j], a1[i], x1[j]);
                }
        }

        // top-8 maintenance (hot path: 1 compare per logit)
#pragma unroll
        for (int i = 0; i < 8; ++i) {
            float*          tv = s_tv + (ty + 8 * i) * 256 + tk_base;
            unsigned short* ti = s_ti + (ty + 8 * i) * 256 + tk_base;
#pragma unroll
            for (int j = 0; j < 4; ++j) {
                unsigned long long v = acc[i][j];
                float s = __uint_as_float((unsigned)v) +
                          __uint_as_float((unsigned)(v >> 32));
                if (s > vmin[i]) {
                    float om = vmin[i];
                    int slot = 7;
#pragma unroll
                    for (int k = 6; k >= 0; --k) if (tv[k] == om) slot = k;
                    tv[slot] = s;
                    ti[slot] = (unsigned short)(tile * TILE_T + tx + 32 * j);
                    float m = tv[0];
#pragma unroll
                    for (int k = 1; k < 8; ++k) m = fminf(m, tv[k]);
                    vmin[i] = m;
                }
            }
        }
    }
    __syncthreads();

    // ---- merge: phase 1, 4 threads/pillar each reduce 64 partial slots to 8
    {
        int pr = t >> 2, q = t & 3;
        float*          src = s_tv + pr * 256 + q * 64;
        unsigned short* si  = s_ti + pr * 256 + q * 64;
        float bv[8]; unsigned short bi[8];
#pragma unroll
        for (int k = 0; k < 8; ++k) {
            float best = -INFINITY; int bs = 0;
            for (int e = 0; e < 64; ++e) {
                float v = src[e];
                if (v > best) { best = v; bs = e; }
            }
            bv[k] = best; bi[k] = si[bs]; src[bs] = -INFINITY;
        }
        __syncthreads();
#pragma unroll
        for (int k = 0; k < 8; ++k) {
            s_tv[pr * 256 + q * 8 + k] = bv[k];
            s_ti[pr * 256 + q * 8 + k] = bi[k];
        }
    }
    __syncthreads();

    // ---- merge: phase 2, one thread/pillar merges 32 -> 8, softmax
    if (t < TILE_P) {
        int pr = t;
        float*          src = s_tv + pr * 256;
        unsigned short* si  = s_ti + pr * 256;
        float fv[8]; int fi[8];
#pragma unroll
        for (int k = 0; k < 8; ++k) {
            float best = -INFINITY; int bs = 0;
            for (int e = 0; e < 32; ++e) {
                float v = src[e];
                if (v > best) { best = v; bs = e; }
            }
            fv[k] = best; fi[k] = si[bs]; src[bs] = -INFINITY;
        }
        float mx = fv[0], ssum = 0.f, w[8];
#pragma unroll
        for (int k = 0; k < 8; ++k) { w[k] = expf(fv[k] - mx); ssum += w[k]; }
        float inv = 1.f / ssum;
#pragma unroll
        for (int k = 0; k < 8; ++k) {
            s_w[pr * 8 + k]  = w[k] * inv;
            s_wi[pr * 8 + k] = fi[k];
        }
    }
    __syncthreads();

    // ---- weighted gather: 4 threads/pillar, 16 dims each
    {
        int pr = t >> 2, seg = (t & 3) << 4;
        if (pr < pvalid) {
            float a[16];
#pragma unroll
            for (int u = 0; u < 16; ++u) a[u] = 0.f;
#pragma unroll
            for (int k = 0; k < 8; ++k) {
                float w = s_w[pr * 8 + k];
                const float* vp = vb + (size_t)s_wi[pr * 8 + k] * D_ + seg;
#pragma unroll
                for (int u = 0; u < 4; ++u) {
                    float4 v = *(const float4*)(vp + u * 4);
                    a[u * 4 + 0] += w * v.x; a[u * 4 + 1] += w * v.y;
                    a[u * 4 + 2] += w * v.z; a[u * 4 + 3] += w * v.w;
                }
            }
            float* op = out_pos + ((size_t)b * P_ + p0 + pr) * D_ + seg;
#pragma unroll
            for (int u = 0; u < 4; ++u)
                *(float4*)(op + u * 4) =
                    make_float4(a[u * 4], a[u * 4 + 1], a[u * 4 + 2], a[u * 4 + 3]);
        }
    }
}

// ---------------------------------------------------------------------------
// zero-fill of the dense grids (streaming stores, evict-first)
// ---------------------------------------------------------------------------
__global__ void zero_kernel(float4* __restrict__ out, size_t n4) {
    size_t i  = (size_t)blockIdx.x * blockDim.x + threadIdx.x;
    size_t st = (size_t)gridDim.x * blockDim.x;
    const float4 z = make_float4(0.f, 0.f, 0.f, 0.f);
    for (; i < n4; i += st) __stcs(out + i, z);
}

__global__ void winner_init_kernel() {
    int i = blockIdx.x * blockDim.x + threadIdx.x;
    if (i < B_ * HW_) g_winner[i] = -1;
}

// duplicate indices: XLA scatter applies updates in order -> last p wins
__global__ void winner_kernel(const int* __restrict__ idx) {
    int i = blockIdx.x * blockDim.x + threadIdx.x;
    if (i < B_ * P_) {
        int b = i / P_;
        atomicMax(&g_winner[b * HW_ + idx[i]], i - b * P_);
    }
}

__global__ void scatter_kernel(const float* __restrict__ pil,
                               const float* __restrict__ scale,
                               const int* __restrict__ idx,
                               float* out) {
    int bp = blockIdx.x;                 // 0 .. B*P-1
    int b = (bp >= P_) ? 1 : 0;
    int p = bp - b * P_;
    int col = idx[bp];
    if (g_winner[b * HW_ + col] != p) return;
    int c = threadIdx.x;                 // 0..63
    float pv = pil[(size_t)bp * D_ + c];
    float sv = scale[(size_t)bp * D_ + c];
    float qv = out[OFF3_ + (size_t)bp * D_ + c];   // pos_point
    float mv = out[OFF4_ + (size_t)bp * D_ + c];   // pos_mem
    size_t g0 = (size_t)b * 128 * HW_ + (size_t)c * HW_ + col;
    out[g0] = pv;                                   // sp[:64] = pillars
    out[g0 + (size_t)64 * HW_] = mv;                // sp[64:] = pos_mem
    out[OFF1_ + g0] = pv;                           // sp_point[:64] = pillars
    out[OFF1_ + g0 + (size_t)64 * HW_] = qv;        // sp_point[64:] = pos_point
    out[OFF2_ + (size_t)b * 64 * HW_ + (size_t)c * HW_ + col] = sv;
}

// ---------------------------------------------------------------------------
extern "C" void kernel_launch(void* const* d_in, const int* in_sizes, int n_in,
                              void* d_out, int out_size) {
    (void)in_sizes; (void)n_in; (void)out_size;
    const float* pillars = (const float*)d_in[0];   // [B,P,64]
    const float* scale   = (const float*)d_in[1];   // [B,P,64]
    const float* points  = (const float*)d_in[2];   // [B,NP,64]
    const float* W       = (const float*)d_in[3];   // [M,64]
    const int*   idx     = (const int*)d_in[4];     // [B,P]
    float* out = (float*)d_out;

    cudaFuncSetAttribute(attn_kernel<NP_>,
                         cudaFuncAttributeMaxDynamicSharedMemorySize, SMEM_BYTES);
    cudaFuncSetAttribute(attn_kernel<M_>,
                         cudaFuncAttributeMaxDynamicSharedMemorySize, SMEM_BYTES);

    winner_init_kernel<<<(B_ * HW_ + 255) / 256, 256>>>();

    dim3 ag((P_ + TILE_P - 1) / TILE_P, B_);        // (63, 2)
    attn_kernel<NP_><<<ag, NTHR, SMEM_BYTES>>>(pillars, points, NP_ * D_, out + OFF3_);
    attn_kernel<M_ ><<<ag, NTHR, SMEM_BYTES>>>(pillars, W, 0, out + OFF4_);

    zero_kernel<<<1184, 256>>>((float4*)out, OFF3_ / 4);

    winner_kernel<<<(B_ * P_ + 255) / 256, 256>>>(idx);
    scatter_kernel<<<B_ * P_, 64>>>(pillars, scale, idx, out);
}

// round 2
// speedup vs baseline: 1.1326x; 1.1326x over previous
#include <cuda_runtime.h>
#include <math.h>

// ---------------------------------------------------------------------------
// Problem constants
// ---------------------------------------------------------------------------
#define B_   2
#define P_   4000
#define NP_  4096
#define D_   64
#define M_   512
#define NX_  432
#define NY_  496
#define HW_  (NX_ * NY_)          // 214272

// Output layout (floats), concatenated in return order:
//   out0 spatial_features        [B,128,HW]
//   out1 spatial_features_point  [B,128,HW]
//   out2 spatial_scale_features  [B, 64,HW]
//   out3 point_positive          [B*P,64]
//   out4 memory_positive         [B*P,64]
#define S0_   ((size_t)B_ * 128 * HW_)
#define S2_   ((size_t)B_ * 64 * HW_)
#define OFF1_ (S0_)
#define OFF2_ (2 * S0_)
#define OFF3_ (2 * S0_ + S2_)                        // 137,134,080 floats to zero
#define OFF4_ (OFF3_ + (size_t)B_ * P_ * D_)

// Tiling
#define TILE_P 64
#define TILE_T 128
#define PITCH  68        // 272 B rows; conflict-free LDS.128, 16B aligned
#define NTHR   256
#define PTILES 63                       // ceil(4000/64)
#define NB_PT  (PTILES * B_)            // 126 point-attention blocks
#define NB_MEM (PTILES * B_)            // 126 memory-attention blocks
#define NB_ATT (NB_PT + NB_MEM)         // 252
#define NB_Z   296                      // zero-fill blocks
#define NB_TOT (NB_ATT + NB_Z)

// dynamic shared layout (bytes)
#define SM_PL   0                                   // 64*68*4      = 17408
#define SM_PT   17408                               // 2*128*68*4   = 69632
#define SM_TKV  87040                               // 64*8*4       =  2048
#define SM_TKI  89088                               // 64*8*4       =  2048
#define SMEM_BYTES 91136

__device__ int g_winner[B_ * HW_];

// ---------------------------------------------------------------------------
__device__ __forceinline__ void cp16(void* dst, const void* src) {
    unsigned a = (unsigned)__cvta_generic_to_shared(dst);
    asm volatile("cp.async.cg.shared.global [%0], [%1], 16;" :: "r"(a), "l"(src));
}
__device__ __forceinline__ void cp_commit() {
    asm volatile("cp.async.commit_group;" ::: "memory");
}
__device__ __forceinline__ void cp_wait_all() {
    asm volatile("cp.async.wait_group 0;" ::: "memory");
}
// packed f32x2 FMA
__device__ __forceinline__ void fma2(unsigned long long& acc,
                                     unsigned long long a, unsigned long long b) {
    asm volatile("fma.rn.f32x2 %0, %1, %2, %0;" : "+l"(acc) : "l"(a), "l"(b));
}

// ---------------------------------------------------------------------------
// One attention block: 64 pillars x npts, top-8 + softmax + weighted gather.
// 256 threads = 8 warps. Warp wy owns pillars [wy*8, wy*8+8): pillar loads are
// warp-uniform broadcasts, and the top-8 list per pillar is warp-private.
// Lane tx owns point rows {tx+32j}. Microtile 8x4, fp32x2-packed FMA.
// ---------------------------------------------------------------------------
__device__ void attn_block(const float* __restrict__ pillars,
                           const float* __restrict__ vecs,
                           int vstride, int npts,
                           float* __restrict__ out_pos,
                           int bid, char* smem)
{
    float* s_pl  = (float*)(smem + SM_PL);
    float* s_pt  = (float*)(smem + SM_PT);
    float* s_tkv = (float*)(smem + SM_TKV);
    int*   s_tki = (int*)(smem + SM_TKI);

    const int t  = threadIdx.x;
    const int tx = t & 31;
    const int wy = t >> 5;
    const int b  = bid / PTILES;
    const int p0 = (bid % PTILES) * TILE_P;
    const int pvalid = min(TILE_P, P_ - p0);
    const float* __restrict__ vb = vecs + (size_t)b * vstride;
    const float* __restrict__ pb = pillars + ((size_t)b * P_ + p0) * D_;
    const unsigned FULL = 0xffffffffu;

    // init top-k slots
    s_tkv[t]       = -INFINITY;
    s_tkv[t + 256] = -INFINITY;

    // prefetch point tile 0
#pragma unroll
    for (int q = 0; q < 8; ++q) {
        int lin = t + q * NTHR;
        int r = lin >> 4, c = (lin & 15) << 2;
        cp16(s_pt + r * PITCH + c, vb + r * D_ + c);
    }
    cp_commit();

    // load pillar tile (zero-pad tail)
#pragma unroll
    for (int q = 0; q < 4; ++q) {
        int lin = t + q * NTHR;
        int r = lin >> 4, c = (lin & 15) << 2;
        float4 v = make_float4(0.f, 0.f, 0.f, 0.f);
        if (r < pvalid) v = *(const float4*)(pb + r * D_ + c);
        *(float4*)(s_pl + r * PITCH + c) = v;
    }
    __syncthreads();

    float vmin[8];
#pragma unroll
    for (int i = 0; i < 8; ++i) vmin[i] = -INFINITY;

    const int NT = npts / TILE_T;
    for (int tile = 0; tile < NT; ++tile) {
        float* buf = s_pt + (tile & 1) * (TILE_T * PITCH);
        cp_wait_all();
        __syncthreads();
        if (tile + 1 < NT) {
            float* nb = s_pt + ((tile + 1) & 1) * (TILE_T * PITCH);
            const float* src = vb + (size_t)(tile + 1) * TILE_T * D_;
#pragma unroll
            for (int q = 0; q < 8; ++q) {
                int lin = t + q * NTHR;
                int r = lin >> 4, c = (lin & 15) << 2;
                cp16(nb + r * PITCH + c, src + r * D_ + c);
            }
            cp_commit();
        }

        unsigned long long acc[8][4];
#pragma unroll
        for (int i = 0; i < 8; ++i)
#pragma unroll
            for (int j = 0; j < 4; ++j) acc[i][j] = 0ull;

#pragma unroll
        for (int dc = 0; dc < D_; dc += 4) {
            ulonglong2 xv[4];
#pragma unroll
            for (int j = 0; j < 4; ++j)
                xv[j] = *(const ulonglong2*)(buf + (tx + 32 * j) * PITCH + dc);
#pragma unroll
            for (int i = 0; i < 8; ++i) {
                ulonglong2 av = *(const ulonglong2*)(s_pl + ((wy << 3) + i) * PITCH + dc);
#pragma unroll
                for (int j = 0; j < 4; ++j) {
                    fma2(acc[i][j], av.x, xv[j].x);
                    fma2(acc[i][j], av.y, xv[j].y);
                }
            }
        }

        // warp-private top-8 maintenance
        const int base = tile * TILE_T;
#pragma unroll
        for (int i = 0; i < 8; ++i) {
            const int pr = (wy << 3) + i;
            float thr = vmin[i];
            float s[4];
#pragma unroll
            for (int j = 0; j < 4; ++j) {
                unsigned long long v = acc[i][j];
                s[j] = __uint_as_float((unsigned)v) +
                       __uint_as_float((unsigned)(v >> 32));
            }
            unsigned any = __ballot_sync(FULL,
                (s[0] > thr) | (s[1] > thr) | (s[2] > thr) | (s[3] > thr));
            if (any) {
                float* tv = s_tkv + pr * 8;
                int*   ti = s_tki + pr * 8;
#pragma unroll
                for (int j = 0; j < 4; ++j) {
                    unsigned m = __ballot_sync(FULL, s[j] > thr);
                    while (m) {
                        int ln = __ffs(m) - 1; m &= m - 1;
                        float v = __shfl_sync(FULL, s[j], ln);
                        if (v > thr) {       // warp-uniform
                            int slot = 0; float mn = tv[0];
#pragma unroll
                            for (int k = 1; k < 8; ++k) {
                                float x = tv[k];
                                if (x < mn) { mn = x; slot = k; }
                            }
                            tv[slot] = v;
                            ti[slot] = base + ln + 32 * j;
                            thr = tv[0];
#pragma unroll
                            for (int k = 1; k < 8; ++k) thr = fminf(thr, tv[k]);
                        }
                    }
                }
                vmin[i] = thr;
            }
        }
    }

    // epilogue: per warp, softmax over its pillars' top-8 + weighted gather
    __syncwarp();
#pragma unroll 1
    for (int i = 0; i < 8; ++i) {
        const int pr = (wy << 3) + i;
        if (pr >= pvalid) break;
        float vals[8]; int id[8];
#pragma unroll
        for (int k = 0; k < 8; ++k) { vals[k] = s_tkv[pr * 8 + k]; id[k] = s_tki[pr * 8 + k]; }
        float mx = vals[0];
#pragma unroll
        for (int k = 1; k < 8; ++k) mx = fmaxf(mx, vals[k]);
        float w[8], ssum = 0.f;
#pragma unroll
        for (int k = 0; k < 8; ++k) { w[k] = expf(vals[k] - mx); ssum += w[k]; }
        float inv = 1.f / ssum;
        float a0 = 0.f, a1 = 0.f;
#pragma unroll
        for (int k = 0; k < 8; ++k) {
            const float* vp = vb + (size_t)id[k] * D_;
            float wk = w[k] * inv;
            a0 += wk * vp[tx];
            a1 += wk * vp[tx + 32];
        }
        float* op = out_pos + ((size_t)b * P_ + p0 + pr) * D_;
        op[tx] = a0;
        op[tx + 32] = a1;
    }
}

// ---------------------------------------------------------------------------
// Fused kernel: attention blocks + zero-fill blocks co-resident (2 blocks/SM)
// so the DRAM-bound zero overlaps the FMA-bound attention.
// ---------------------------------------------------------------------------
__global__ void __launch_bounds__(NTHR, 2)
fused_kernel(const float* __restrict__ pillars,
             const float* __restrict__ points,
             const float* __restrict__ W,
             float* __restrict__ out)
{
    extern __shared__ char smem[];
    const int role = blockIdx.x;
    if (role < NB_ATT) {
        const int isMem = role >= NB_PT;
        const int bid = isMem ? role - NB_PT : role;
        attn_block(pillars,
                   isMem ? W : points,
                   isMem ? 0 : NP_ * D_,
                   isMem ? M_ : NP_,
                   out + (isMem ? OFF4_ : OFF3_),
                   bid, smem);
    } else {
        const int zr = role - NB_ATT;
        const int t = threadIdx.x;
        float4* o4 = (float4*)out;
        const size_t n4 = OFF3_ / 4;
        const size_t stride = (size_t)NB_Z * NTHR;
        const float4 z = make_float4(0.f, 0.f, 0.f, 0.f);
        for (size_t i = (size_t)zr * NTHR + t; i < n4; i += stride)
            __stcs(o4 + i, z);
        for (int i = zr * NTHR + t; i < B_ * HW_; i += NB_Z * NTHR)
            g_winner[i] = -1;
    }
}

// duplicate indices: scatter applies updates in order -> last p wins
__global__ void winner_kernel(const int* __restrict__ idx) {
    int i = blockIdx.x * blockDim.x + threadIdx.x;
    if (i < B_ * P_) {
        int b = i / P_;
        atomicMax(&g_winner[b * HW_ + idx[i]], i - b * P_);
    }
}

__global__ void scatter_kernel(const float* __restrict__ pil,
                               const float* __restrict__ scale,
                               const int* __restrict__ idx,
                               float* out) {
    int bp = blockIdx.x;                 // 0 .. B*P-1
    int b = (bp >= P_) ? 1 : 0;
    int p = bp - b * P_;
    int col = idx[bp];
    if (g_winner[b * HW_ + col] != p) return;
    int c = threadIdx.x;                 // 0..63
    float pv = pil[(size_t)bp * D_ + c];
    float sv = scale[(size_t)bp * D_ + c];
    float qv = out[OFF3_ + (size_t)bp * D_ + c];   // pos_point
    float mv = out[OFF4_ + (size_t)bp * D_ + c];   // pos_mem
    size_t g0 = (size_t)b * 128 * HW_ + (size_t)c * HW_ + col;
    out[g0] = pv;                                   // sp[:64]
    out[g0 + (size_t)64 * HW_] = mv;                // sp[64:]
    out[OFF1_ + g0] = pv;                           // sp_point[:64]
    out[OFF1_ + g0 + (size_t)64 * HW_] = qv;        // sp_point[64:]
    out[OFF2_ + (size_t)b * 64 * HW_ + (size_t)c * HW_ + col] = sv;
}

// ---------------------------------------------------------------------------
extern "C" void kernel_launch(void* const* d_in, const int* in_sizes, int n_in,
                              void* d_out, int out_size) {
    (void)in_sizes; (void)n_in; (void)out_size;
    const float* pillars = (const float*)d_in[0];
    const float* scale   = (const float*)d_in[1];
    const float* points  = (const float*)d_in[2];
    const float* W       = (const float*)d_in[3];
    const int*   idx     = (const int*)d_in[4];
    float* out = (float*)d_out;

    cudaFuncSetAttribute(fused_kernel,
                         cudaFuncAttributeMaxDynamicSharedMemorySize, SMEM_BYTES);

    fused_kernel<<<NB_TOT, NTHR, SMEM_BYTES>>>(pillars, points, W, out);
    winner_kernel<<<(B_ * P_ + 255) / 256, 256>>>(idx);
    scatter_kernel<<<B_ * P_, 64>>>(pillars, scale, idx, out);
}